// round 1
// baseline (speedup 1.0000x reference)
#include <cuda_runtime.h>
#include <math.h>

#define Bb 128
#define Mm 200
#define Ss 20
#define Qq 20
#define Vv 50000
#define Dd 128
#define NT 4          // max_hops + 1 tables
#define RU 130        // padded row (floats) for U tile in smem
#define RE 130        // padded row (floats) for E tile in smem
#define GEMM_SMEM ((128*RU + 64*RE)*4)   // 99,840 bytes

// -------- device scratch (static allocation; no cudaMalloc allowed) --------
__device__ float g_u[Bb * Dd];                              // 64 KB
__device__ float g_mt[(long)NT * Bb * Mm * Dd];             // 52.4 MB

// ============================================================
// Kernel 1: u = sum over query tokens of E[0] rows.  grid=B, block=D
// ============================================================
__global__ void k_query_u(const int* __restrict__ query,
                          const float* __restrict__ E) {
    int b = blockIdx.x, d = threadIdx.x;
    __shared__ int q[Qq];
    if (d < Qq) q[d] = query[b * Qq + d];
    __syncthreads();
    float acc = 0.f;
#pragma unroll
    for (int i = 0; i < Qq; i++)
        acc += E[(long)q[i] * Dd + d];
    g_u[b * Dd + d] = acc;
}

// ============================================================
// Kernel 2: mt[t][b][i][d] = sum_s E[t][story[b,i,s]][d] + T[t][i][d]
// grid = B*M blocks, block = D threads. All 4 tables per block (index reuse).
// ============================================================
__global__ void k_story_sums(const int* __restrict__ story,
                             const float* __restrict__ E,
                             const float* __restrict__ T) {
    int blk = blockIdx.x;
    int b = blk / Mm, i = blk - b * Mm;
    int d = threadIdx.x;
    __shared__ int idx[Ss];
    if (d < Ss) idx[d] = story[((long)b * Mm + i) * Ss + d];
    __syncthreads();
#pragma unroll
    for (int t = 0; t < NT; t++) {
        const float* Et = E + (long)t * Vv * Dd;
        float acc = T[((long)t * Mm + i) * Dd + d];
#pragma unroll
        for (int s = 0; s < Ss; s++)
            acc += Et[(long)idx[s] * Dd + d];
        g_mt[(((long)t * Bb + b) * Mm + i) * Dd + d] = acc;
    }
}

// ============================================================
// Kernel 3: all 3 hops fused. grid=B, block=256. u lives in smem.
// ============================================================
__global__ void k_hops() {
    __shared__ float su[Dd];
    __shared__ float sc[Mm];
    __shared__ float red[32];
    __shared__ float op[256];
    int b = blockIdx.x, tid = threadIdx.x;
    int w = tid >> 5, lane = tid & 31;

    if (tid < Dd) su[tid] = g_u[b * Dd + tid];
    __syncthreads();

    for (int hop = 0; hop < NT - 1; hop++) {
        // ---- scores[i] = dot(mt[hop][b][i], u) ; warp per i ----
        const float* mt = g_mt + (((long)hop * Bb + b) * Mm) * Dd;
        float4 uu = ((const float4*)su)[lane];
        for (int i = w; i < Mm; i += 8) {
            const float4* row = (const float4*)(mt + (long)i * Dd);
            float4 r = row[lane];
            float p = r.x * uu.x + r.y * uu.y + r.z * uu.z + r.w * uu.w;
#pragma unroll
            for (int o = 16; o; o >>= 1) p += __shfl_xor_sync(0xffffffffu, p, o);
            if (lane == 0) sc[i] = p;
        }
        __syncthreads();

        // ---- softmax over M=200 ----
        float v = (tid < Mm) ? sc[tid] : -INFINITY;
        float m = v;
#pragma unroll
        for (int o = 16; o; o >>= 1) m = fmaxf(m, __shfl_xor_sync(0xffffffffu, m, o));
        if (lane == 0) red[w] = m;
        __syncthreads();
        if (tid == 0) {
            float mm = red[0];
            for (int k = 1; k < 8; k++) mm = fmaxf(mm, red[k]);
            red[8] = mm;
        }
        __syncthreads();
        float gmax = red[8];
        float e = (tid < Mm) ? expf(v - gmax) : 0.f;
        float s = e;
#pragma unroll
        for (int o = 16; o; o >>= 1) s += __shfl_xor_sync(0xffffffffu, s, o);
        if (lane == 0) red[16 + w] = s;
        __syncthreads();
        if (tid == 0) {
            float ssum = 0.f;
            for (int k = 0; k < 8; k++) ssum += red[16 + k];
            red[9] = 1.f / ssum;
        }
        __syncthreads();
        if (tid < Mm) sc[tid] = e * red[9];
        __syncthreads();

        // ---- o[d] = sum_i p[i] * mt[hop+1][b][i][d]; u += o ----
        const float* mtn = g_mt + (((long)(hop + 1) * Bb + b) * Mm) * Dd;
        int half = tid >> 7;
        int d = tid & 127;
        float acc = 0.f;
        int i0 = half * (Mm / 2);
        for (int i = i0; i < i0 + Mm / 2; i++)
            acc += sc[i] * mtn[(long)i * Dd + d];
        op[tid] = acc;
        __syncthreads();
        if (tid < Dd) su[tid] += op[tid] + op[Dd + tid];
        __syncthreads();
    }
    if (tid < Dd) g_u[b * Dd + tid] = su[tid];
}

// ============================================================
// Kernel 4: ahat[b][v] = dot(u[b], E3[v]).  Tile 128b x 64v per block,
// 128 threads, 8x8 per-thread register tile, packed fma.rn.f32x2 along K.
// Bank-conflict-free layouts (pad=130; checked per 16-lane LDS.64 phase).
// ============================================================
__global__ void __launch_bounds__(128, 2)
k_gemm(const float* __restrict__ E3, float* __restrict__ ahat) {
    extern __shared__ float sm[];
    float* sU = sm;              // [128][RU]
    float* sE = sm + 128 * RU;   // [64][RE]
    int tid = threadIdx.x;
    int v0 = blockIdx.x * 64;

    // load U (all 128 rows) — 8192 float2
    const float2* gU2 = (const float2*)g_u;
#pragma unroll
    for (int it = 0; it < 64; it++) {
        int e = tid + it * 128;
        int bb = e >> 6, kk = e & 63;
        float2 val = gU2[e];
        *(float2*)(sU + bb * RU + kk * 2) = val;
    }
    // load E tile (64 v rows) — 4096 float2, zero-pad past V
    const float2* gE2 = (const float2*)E3;
#pragma unroll
    for (int it = 0; it < 32; it++) {
        int e = tid + it * 128;
        int vv = e >> 6, kk = e & 63;
        long vg = (long)v0 + vv;
        float2 val = (vg < Vv) ? gE2[vg * 64 + kk] : make_float2(0.f, 0.f);
        *(float2*)(sE + vv * RE + kk * 2) = val;
    }
    __syncthreads();

    int tv = tid & 7;     // v lanes: v = tv + 8*jv  (phase-distinct banks)
    int tb = tid >> 3;    // b lanes: b = tb*8 + jb  (2 addrs, distinct banks)

    unsigned long long acc[8][8];
#pragma unroll
    for (int i = 0; i < 8; i++)
#pragma unroll
        for (int j = 0; j < 8; j++) acc[i][j] = 0ull;

    const unsigned long long* sU64 = (const unsigned long long*)sU;
    const unsigned long long* sE64 = (const unsigned long long*)sE;

#pragma unroll 2
    for (int k2 = 0; k2 < 64; k2++) {
        unsigned long long u2[8], e2[8];
#pragma unroll
        for (int jb = 0; jb < 8; jb++) u2[jb] = sU64[(tb * 8 + jb) * 65 + k2];
#pragma unroll
        for (int jv = 0; jv < 8; jv++) e2[jv] = sE64[(tv + 8 * jv) * 65 + k2];
#pragma unroll
        for (int jb = 0; jb < 8; jb++)
#pragma unroll
            for (int jv = 0; jv < 8; jv++)
                asm("fma.rn.f32x2 %0, %1, %2, %0;"
                    : "+l"(acc[jb][jv]) : "l"(u2[jb]), "l"(e2[jv]));
    }

#pragma unroll
    for (int jb = 0; jb < 8; jb++) {
        int bb = tb * 8 + jb;
#pragma unroll
        for (int jv = 0; jv < 8; jv++) {
            int vv = v0 + tv + 8 * jv;
            if (vv < Vv) {
                float2 f = *(float2*)&acc[jb][jv];
                ahat[(long)bb * Vv + vv] = f.x + f.y;
            }
        }
    }
}

// ============================================================
// Kernel 5: row softmax over V=50000. grid=B, block=1024.
// ============================================================
__global__ void k_softmax_v(const float* __restrict__ ahat,
                            float* __restrict__ proba) {
    __shared__ float red[32];
    int b = blockIdx.x, tid = threadIdx.x;
    int lane = tid & 31, w = tid >> 5;
    const float* row = ahat + (long)b * Vv;

    float m = -INFINITY;
    for (int v = tid; v < Vv; v += 1024) m = fmaxf(m, row[v]);
#pragma unroll
    for (int o = 16; o; o >>= 1) m = fmaxf(m, __shfl_xor_sync(0xffffffffu, m, o));
    if (lane == 0) red[w] = m;
    __syncthreads();
    if (w == 0) {
        float t = red[lane];
#pragma unroll
        for (int o = 16; o; o >>= 1) t = fmaxf(t, __shfl_xor_sync(0xffffffffu, t, o));
        if (lane == 0) red[0] = t;
    }
    __syncthreads();
    float gmax = red[0];
    __syncthreads();

    float s = 0.f;
    for (int v = tid; v < Vv; v += 1024) s += expf(row[v] - gmax);
#pragma unroll
    for (int o = 16; o; o >>= 1) s += __shfl_xor_sync(0xffffffffu, s, o);
    if (lane == 0) red[w] = s;
    __syncthreads();
    if (w == 0) {
        float t = red[lane];
#pragma unroll
        for (int o = 16; o; o >>= 1) t += __shfl_xor_sync(0xffffffffu, t, o);
        if (lane == 0) red[0] = t;
    }
    __syncthreads();
    float inv = 1.f / red[0];

    float* prow = proba + (long)b * Vv;
    for (int v = tid; v < Vv; v += 1024)
        prow[v] = expf(row[v] - gmax) * inv;
}

// ============================================================
extern "C" void kernel_launch(void* const* d_in, const int* in_sizes, int n_in,
                              void* d_out, int out_size) {
    // match inputs by element count (robust to metadata ordering)
    const int* story = nullptr;
    const int* query = nullptr;
    const float* E = nullptr;
    const float* T = nullptr;
    for (int i = 0; i < n_in; i++) {
        long n = in_sizes[i];
        if (n == (long)Bb * Mm * Ss) story = (const int*)d_in[i];
        else if (n == (long)Bb * Qq) query = (const int*)d_in[i];
        else if (n == (long)NT * Vv * Dd) E = (const float*)d_in[i];
        else if (n == (long)NT * Mm * Dd) T = (const float*)d_in[i];
    }
    float* out = (float*)d_out;
    long BV = (long)Bb * Vv;

    k_query_u<<<Bb, Dd>>>(query, E);
    k_story_sums<<<Bb * Mm, Dd>>>(story, E, T);
    k_hops<<<Bb, 256>>>();

    const float* E3 = E + (long)(NT - 1) * Vv * Dd;
    cudaFuncSetAttribute(k_gemm, cudaFuncAttributeMaxDynamicSharedMemorySize,
                         GEMM_SMEM);
    k_gemm<<<(Vv + 63) / 64, 128, GEMM_SMEM>>>(E3, out);

    if ((long)out_size >= 2 * BV)
        k_softmax_v<<<Bb, 1024>>>(out, out + BV);
}

// round 3
// speedup vs baseline: 2.1584x; 2.1584x over previous
#include <cuda_runtime.h>
#include <math.h>
#include <stdint.h>

#define Bb 128
#define Mm 200
#define Ss 20
#define Qq 20
#define Vv 50000
#define Dd 128
#define NT 4          // max_hops + 1 tables

// -------- device scratch (static allocation; no cudaMalloc allowed) --------
__device__ float g_u[Bb * Dd];                              // 64 KB
__device__ float g_mt[(long)NT * Bb * Mm * Dd];             // 52.4 MB

// ============================================================
// Kernel 1: u = sum over query tokens of E[0] rows.  grid=B, block=D
// ============================================================
__global__ void k_query_u(const int* __restrict__ query,
                          const float* __restrict__ E) {
    int b = blockIdx.x, d = threadIdx.x;
    __shared__ int q[Qq];
    if (d < Qq) q[d] = query[b * Qq + d];
    __syncthreads();
    float acc = 0.f;
#pragma unroll
    for (int i = 0; i < Qq; i++)
        acc += E[(long)q[i] * Dd + d];
    g_u[b * Dd + d] = acc;
}

// ============================================================
// Kernel 2: mt[t][b][i][d] = sum_s E[t][story[b,i,s]][d] + T[t][i][d]
// One warp per (t,b,i). Grid ordered TABLE-MAJOR so one 25.6MB table is
// hot in L2 at a time. 8 warps / block.
// ============================================================
#define SS_WPB 8
__global__ void __launch_bounds__(SS_WPB * 32) k_story_sums(
        const int* __restrict__ story,
        const float* __restrict__ E,
        const float* __restrict__ T) {
    long gw = (long)blockIdx.x * SS_WPB + (threadIdx.x >> 5);
    int lane = threadIdx.x & 31;
    int t = (int)(gw / ((long)Bb * Mm));
    int rem = (int)(gw - (long)t * Bb * Mm);
    int b = rem / Mm, i = rem - b * Mm;

    int tok = (lane < Ss) ? story[((long)b * Mm + i) * Ss + lane] : 0;

    const float4* Et = (const float4*)(E + (long)t * Vv * Dd);
    float4 acc = ((const float4*)(T + ((long)t * Mm + i) * Dd))[lane];
#pragma unroll
    for (int s = 0; s < Ss; s++) {
        int id = __shfl_sync(0xffffffffu, tok, s);
        float4 r = Et[(long)id * 32 + lane];
        acc.x += r.x; acc.y += r.y; acc.z += r.z; acc.w += r.w;
    }
    ((float4*)(g_mt + (((long)t * Bb + b) * Mm + i) * Dd))[lane] = acc;
}

// ============================================================
// Kernel 3: all 3 hops fused. grid=B, block=1024. u lives in smem.
// ============================================================
__global__ void __launch_bounds__(1024) k_hops() {
    __shared__ float su[Dd];
    __shared__ float sc[Mm];
    __shared__ float red[32];
    __shared__ float bc[2];
    __shared__ float op[1024];
    int b = blockIdx.x, tid = threadIdx.x;
    int w = tid >> 5, lane = tid & 31;

    if (tid < Dd) su[tid] = g_u[b * Dd + tid];
    __syncthreads();

    for (int hop = 0; hop < NT - 1; hop++) {
        // ---- scores[i] = dot(mt[hop][b][i], u); warp per i ----
        const float* mt = g_mt + (((long)hop * Bb + b) * Mm) * Dd;
        float4 uu = ((const float4*)su)[lane];
        for (int i = w; i < Mm; i += 32) {
            const float4* row = (const float4*)(mt + (long)i * Dd);
            float4 r = row[lane];
            float p = r.x * uu.x + r.y * uu.y + r.z * uu.z + r.w * uu.w;
#pragma unroll
            for (int o = 16; o; o >>= 1) p += __shfl_xor_sync(0xffffffffu, p, o);
            if (lane == 0) sc[i] = p;
        }
        __syncthreads();

        // ---- softmax over M=200 ----
        float v = (tid < Mm) ? sc[tid] : -INFINITY;
        float m = v;
#pragma unroll
        for (int o = 16; o; o >>= 1) m = fmaxf(m, __shfl_xor_sync(0xffffffffu, m, o));
        if (lane == 0) red[w] = m;
        __syncthreads();
        if (w == 0) {
            float t = red[lane];
#pragma unroll
            for (int o = 16; o; o >>= 1) t = fmaxf(t, __shfl_xor_sync(0xffffffffu, t, o));
            if (lane == 0) bc[0] = t;
        }
        __syncthreads();
        float e = (tid < Mm) ? expf(v - bc[0]) : 0.f;
        float s = e;
#pragma unroll
        for (int o = 16; o; o >>= 1) s += __shfl_xor_sync(0xffffffffu, s, o);
        if (lane == 0) red[w] = s;
        __syncthreads();
        if (w == 0) {
            float t = red[lane];
#pragma unroll
            for (int o = 16; o; o >>= 1) t += __shfl_xor_sync(0xffffffffu, t, o);
            if (lane == 0) bc[1] = 1.f / t;
        }
        __syncthreads();
        if (tid < Mm) sc[tid] = e * bc[1];
        __syncthreads();

        // ---- o[d] = sum_i p[i] * mt[hop+1][b][i][d]; 8-way i-split ----
        const float* mtn = g_mt + (((long)(hop + 1) * Bb + b) * Mm) * Dd;
        int part = tid >> 7, d = tid & 127;
        float acc = 0.f;
        int i0 = part * 25;
#pragma unroll
        for (int i = i0; i < i0 + 25; i++)
            acc += sc[i] * mtn[(long)i * Dd + d];
        op[tid] = acc;
        __syncthreads();
        if (tid < Dd) {
            float o = 0.f;
#pragma unroll
            for (int p = 0; p < 8; p++) o += op[p * 128 + tid];
            su[tid] += o;
        }
        __syncthreads();
    }
    if (tid < Dd) g_u[b * Dd + tid] = su[tid];
}

// ============================================================
// Kernel 4: ahat = u @ E3^T via mma.sync m16n8k8 TF32 with 3xTF32
// error compensation (hi*hi + hi*lo + lo*hi) -> fp32-class accuracy.
// Block: 128(M=batch) x 64(N=vocab), 256 threads (8 warps, 4x2).
// ============================================================
#define PITCH 132     // padded smem row (floats): conflict-free frag loads
#define GSM_BYTES ((128 * PITCH + 64 * PITCH) * 4)   // 101376 B

__device__ __forceinline__ void tf32_split(float x, uint32_t& hi, uint32_t& lo) {
    asm("cvt.rna.tf32.f32 %0, %1;" : "=r"(hi) : "f"(x));
    float l = x - __uint_as_float(hi);
    asm("cvt.rna.tf32.f32 %0, %1;" : "=r"(lo) : "f"(l));
}
#define MMA_TF32(c, a0, a1, a2, a3, b0, b1) \
    asm volatile("mma.sync.aligned.m16n8k8.row.col.f32.tf32.tf32.f32 " \
        "{%0,%1,%2,%3}, {%4,%5,%6,%7}, {%8,%9}, {%0,%1,%2,%3};" \
        : "+f"((c)[0]), "+f"((c)[1]), "+f"((c)[2]), "+f"((c)[3]) \
        : "r"(a0), "r"(a1), "r"(a2), "r"(a3), "r"(b0), "r"(b1))

__global__ void __launch_bounds__(256, 1)
k_gemm_mma(const float* __restrict__ E3, float* __restrict__ ahat) {
    extern __shared__ float sm[];
    float* sA = sm;               // [128][PITCH]
    float* sB = sm + 128 * PITCH; // [64][PITCH]
    int tid = threadIdx.x, lane = tid & 31, wid = tid >> 5;
    int wm = wid & 3, wn = wid >> 2;     // warp tile: 32M x 32N
    int v0 = blockIdx.x * 64;

    // load A = g_u [128 x 128]
    const float4* gu = (const float4*)g_u;
#pragma unroll
    for (int it = 0; it < 16; it++) {
        int e = tid + it * 256;
        int row = e >> 5, c4 = e & 31;
        *(float4*)(sA + row * PITCH + c4 * 4) = gu[e];
    }
    // load B tile = E3 rows [v0, v0+64), zero-pad past V
    const float4* ge = (const float4*)E3;
#pragma unroll
    for (int it = 0; it < 8; it++) {
        int e = tid + it * 256;
        int row = e >> 5, c4 = e & 31;
        long v = (long)v0 + row;
        float4 val = (v < Vv) ? ge[v * 32 + c4] : make_float4(0.f, 0.f, 0.f, 0.f);
        *(float4*)(sB + row * PITCH + c4 * 4) = val;
    }
    __syncthreads();

    float acc[2][4][4];
#pragma unroll
    for (int i = 0; i < 2; i++)
#pragma unroll
        for (int j = 0; j < 4; j++)
#pragma unroll
            for (int k = 0; k < 4; k++) acc[i][j][k] = 0.f;

    int g = lane >> 2, tg = lane & 3;    // groupID, thread-in-group

#pragma unroll 2
    for (int ks = 0; ks < 16; ks++) {
        int k0 = ks * 8 + tg;
        // A fragments (2 m-tiles), split to tf32 hi/lo
        uint32_t ah[2][4], al[2][4];
#pragma unroll
        for (int mt = 0; mt < 2; mt++) {
            const float* pr = sA + (wm * 32 + mt * 16 + g) * PITCH;
            float a0 = pr[k0];
            float a1 = pr[8 * PITCH + k0];
            float a2 = pr[k0 + 4];
            float a3 = pr[8 * PITCH + k0 + 4];
            tf32_split(a0, ah[mt][0], al[mt][0]);
            tf32_split(a1, ah[mt][1], al[mt][1]);
            tf32_split(a2, ah[mt][2], al[mt][2]);
            tf32_split(a3, ah[mt][3], al[mt][3]);
        }
#pragma unroll
        for (int nt = 0; nt < 4; nt++) {
            const float* pb = sB + (wn * 32 + nt * 8 + g) * PITCH;
            float b0 = pb[k0], b1 = pb[k0 + 4];
            uint32_t bh0, bl0, bh1, bl1;
            tf32_split(b0, bh0, bl0);
            tf32_split(b1, bh1, bl1);
#pragma unroll
            for (int mt = 0; mt < 2; mt++) {
                MMA_TF32(acc[mt][nt], ah[mt][0], ah[mt][1], ah[mt][2], ah[mt][3], bh0, bh1);
                MMA_TF32(acc[mt][nt], ah[mt][0], ah[mt][1], ah[mt][2], ah[mt][3], bl0, bl1);
                MMA_TF32(acc[mt][nt], al[mt][0], al[mt][1], al[mt][2], al[mt][3], bh0, bh1);
            }
        }
    }

    // Epilogue: float2 stores
#pragma unroll
    for (int mt = 0; mt < 2; mt++) {
        int m = wm * 32 + mt * 16 + g;
#pragma unroll
        for (int nt = 0; nt < 4; nt++) {
            int v = v0 + wn * 32 + nt * 8 + 2 * tg;
            if (v < Vv) {
                *(float2*)(ahat + (long)m * Vv + v) =
                    make_float2(acc[mt][nt][0], acc[mt][nt][1]);
                *(float2*)(ahat + (long)(m + 8) * Vv + v) =
                    make_float2(acc[mt][nt][2], acc[mt][nt][3]);
            }
        }
    }
}

// ============================================================
// Kernel 5: row softmax over V=50000. grid=B, block=1024.
// ============================================================
__global__ void k_softmax_v(const float* __restrict__ ahat,
                            float* __restrict__ proba) {
    __shared__ float red[32];
    int b = blockIdx.x, tid = threadIdx.x;
    int lane = tid & 31, w = tid >> 5;
    const float* row = ahat + (long)b * Vv;

    float m = -INFINITY;
    for (int v = tid; v < Vv; v += 1024) m = fmaxf(m, row[v]);
#pragma unroll
    for (int o = 16; o; o >>= 1) m = fmaxf(m, __shfl_xor_sync(0xffffffffu, m, o));
    if (lane == 0) red[w] = m;
    __syncthreads();
    if (w == 0) {
        float t = red[lane];
#pragma unroll
        for (int o = 16; o; o >>= 1) t = fmaxf(t, __shfl_xor_sync(0xffffffffu, t, o));
        if (lane == 0) red[0] = t;
    }
    __syncthreads();
    float gmax = red[0];
    __syncthreads();

    float s = 0.f;
    for (int v = tid; v < Vv; v += 1024) s += expf(row[v] - gmax);
#pragma unroll
    for (int o = 16; o; o >>= 1) s += __shfl_xor_sync(0xffffffffu, s, o);
    if (lane == 0) red[w] = s;
    __syncthreads();
    if (w == 0) {
        float t = red[lane];
#pragma unroll
        for (int o = 16; o; o >>= 1) t += __shfl_xor_sync(0xffffffffu, t, o);
        if (lane == 0) red[0] = t;
    }
    __syncthreads();
    float inv = 1.f / red[0];

    float* prow = proba + (long)b * Vv;
    for (int v = tid; v < Vv; v += 1024)
        prow[v] = expf(row[v] - gmax) * inv;
}

// ============================================================
extern "C" void kernel_launch(void* const* d_in, const int* in_sizes, int n_in,
                              void* d_out, int out_size) {
    const int* story = nullptr;
    const int* query = nullptr;
    const float* E = nullptr;
    const float* T = nullptr;
    for (int i = 0; i < n_in; i++) {
        long n = in_sizes[i];
        if (n == (long)Bb * Mm * Ss) story = (const int*)d_in[i];
        else if (n == (long)Bb * Qq) query = (const int*)d_in[i];
        else if (n == (long)NT * Vv * Dd) E = (const float*)d_in[i];
        else if (n == (long)NT * Mm * Dd) T = (const float*)d_in[i];
    }
    float* out = (float*)d_out;
    long BV = (long)Bb * Vv;

    k_query_u<<<Bb, Dd>>>(query, E);
    long nwarps = (long)NT * Bb * Mm;                 // 102400 warps
    k_story_sums<<<(int)(nwarps / SS_WPB), SS_WPB * 32>>>(story, E, T);
    k_hops<<<Bb, 1024>>>();

    const float* E3 = E + (long)(NT - 1) * Vv * Dd;
    cudaFuncSetAttribute(k_gemm_mma, cudaFuncAttributeMaxDynamicSharedMemorySize,
                         GSM_BYTES);
    k_gemm_mma<<<(Vv + 63) / 64, 256, GSM_BYTES>>>(E3, out);

    if ((long)out_size >= 2 * BV)
        k_softmax_v<<<Bb, 1024>>>(out, out + BV);
}